// round 5
// baseline (speedup 1.0000x reference)
#include <cuda_runtime.h>
#include <cuda_bf16.h>
#include <cstdint>

#define NB 8
#define NT 2048
#define NC 1024
#define NH 64
#define PSTR 36   // u64 row stride for all pair-tiles (32 k-pairs + 4 pad)

typedef unsigned long long u64;

// scratch (allocation-free rule: __device__ globals)
__device__ float g_q[NB * NT * NH];
__device__ float g_k[NB * NT * NH];
__device__ float g_v[NB * NT * NH];

// ---- bf16 hi/lo split helpers -------------------------------------------
// u64 layout: low 32 bits = (bf16 hi of k0 | hi of k1 << 16), high 32 = lo pair.
__device__ __forceinline__ u64 bsplit2(float a, float b) {
    __nv_bfloat162 h = __floats2bfloat162_rn(a, b);
    float2 hf = __bfloat1622float2(h);
    __nv_bfloat162 l = __floats2bfloat162_rn(a - hf.x, b - hf.y);
    uint32_t hu = *reinterpret_cast<uint32_t*>(&h);
    uint32_t lu = *reinterpret_cast<uint32_t*>(&l);
    u64 r;
    asm("mov.b64 %0, {%1,%2};" : "=l"(r) : "r"(hu), "r"(lu));
    return r;
}
__device__ __forceinline__ void up2(u64 v, uint32_t& h, uint32_t& l) {
    asm("mov.b64 {%0,%1}, %2;" : "=r"(h), "=r"(l) : "l"(v));
}
__device__ __forceinline__ void mma4(float* c, const uint32_t* a, const uint32_t* b) {
    asm volatile(
        "mma.sync.aligned.m16n8k16.row.col.f32.bf16.bf16.f32 "
        "{%0,%1,%2,%3}, {%4,%5,%6,%7}, {%8,%9}, {%0,%1,%2,%3};"
        : "+f"(c[0]), "+f"(c[1]), "+f"(c[2]), "+f"(c[3])
        : "r"(a[0]), "r"(a[1]), "r"(a[2]), "r"(a[3]), "r"(b[0]), "r"(b[1]));
}

// ---------------------------------------------------------------------------
// Projection: out[t][h] = sum_c x[t][c] * W[h][c], via bf16x2 split mma.sync.
// grid (128, 3): 128 M-tiles of 128 rows; y selects (Wk,Wq,Wv) -> (g_k,g_q,g_v).
// block 256 = 8 warps: warp_m = wid&3 (32 rows), warp_n = wid>>2 (32 cols).
// K chunks of 64, double-buffered smem, global loads staged through registers.
// ---------------------------------------------------------------------------
__global__ __launch_bounds__(256, 1) void proj_kernel(
    const float* __restrict__ x, const float* __restrict__ Wk,
    const float* __restrict__ Wq, const float* __restrict__ Wv)
{
    extern __shared__ u64 smp[];
    u64* Abuf = smp;                    // [2][128][PSTR]
    u64* Bbuf = smp + 2 * 128 * PSTR;   // [2][64][PSTR]

    const float* __restrict__ W;
    float* out;
    if (blockIdx.y == 0)      { W = Wk; out = g_k; }
    else if (blockIdx.y == 1) { W = Wq; out = g_q; }
    else                      { W = Wv; out = g_v; }

    const int tid = threadIdx.x;
    const int lane = tid & 31, wid = tid >> 5;
    const int g = lane >> 2, t = lane & 3;
    const int wm = wid & 3, wn = wid >> 2;
    const long tile = (long)blockIdx.x * 128;

    float acc[2][4][4];
#pragma unroll
    for (int i = 0; i < 2; i++)
#pragma unroll
        for (int j = 0; j < 4; j++)
#pragma unroll
            for (int e = 0; e < 4; e++) acc[i][j][e] = 0.f;

    float4 ra[8], rb[4];
    auto ldg_chunk = [&](int c) {
        const int k0 = c * 64;
#pragma unroll
        for (int it = 0; it < 8; it++) {
            int idx = tid + 256 * it;
            int r = idx >> 4, c4 = idx & 15;
            ra[it] = *(const float4*)(x + (tile + r) * NC + k0 + c4 * 4);
        }
#pragma unroll
        for (int it = 0; it < 4; it++) {
            int idx = tid + 256 * it;
            int r = idx >> 4, c4 = idx & 15;
            rb[it] = *(const float4*)(W + (long)r * NC + k0 + c4 * 4);
        }
    };
    auto sts_chunk = [&](int buf) {
        u64* Ab = Abuf + buf * 128 * PSTR;
        u64* Bb = Bbuf + buf * 64 * PSTR;
#pragma unroll
        for (int it = 0; it < 8; it++) {
            int idx = tid + 256 * it;
            int r = idx >> 4, c4 = idx & 15;
            ulonglong2 st;
            st.x = bsplit2(ra[it].x, ra[it].y);
            st.y = bsplit2(ra[it].z, ra[it].w);
            *reinterpret_cast<ulonglong2*>(&Ab[r * PSTR + 2 * c4]) = st;
        }
#pragma unroll
        for (int it = 0; it < 4; it++) {
            int idx = tid + 256 * it;
            int r = idx >> 4, c4 = idx & 15;
            ulonglong2 st;
            st.x = bsplit2(rb[it].x, rb[it].y);
            st.y = bsplit2(rb[it].z, rb[it].w);
            *reinterpret_cast<ulonglong2*>(&Bb[r * PSTR + 2 * c4]) = st;
        }
    };

    ldg_chunk(0);
    sts_chunk(0);
    __syncthreads();

    for (int c = 0; c < 16; c++) {
        if (c + 1 < 16) ldg_chunk(c + 1);

        const u64* Ab = Abuf + (c & 1) * 128 * PSTR;
        const u64* Bb = Bbuf + (c & 1) * 64 * PSTR;
#pragma unroll
        for (int ks = 0; ks < 4; ks++) {
            uint32_t ah[2][4], al[2][4];
#pragma unroll
            for (int i = 0; i < 2; i++) {
                int row = wm * 32 + i * 16 + g;
                up2(Ab[row * PSTR + 8 * ks + t],           ah[i][0], al[i][0]);
                up2(Ab[(row + 8) * PSTR + 8 * ks + t],     ah[i][1], al[i][1]);
                up2(Ab[row * PSTR + 8 * ks + t + 4],       ah[i][2], al[i][2]);
                up2(Ab[(row + 8) * PSTR + 8 * ks + t + 4], ah[i][3], al[i][3]);
            }
#pragma unroll
            for (int j = 0; j < 4; j++) {
                int n = wn * 32 + j * 8 + g;
                uint32_t bh[2], bl[2];
                up2(Bb[n * PSTR + 8 * ks + t],     bh[0], bl[0]);
                up2(Bb[n * PSTR + 8 * ks + t + 4], bh[1], bl[1]);
#pragma unroll
                for (int i = 0; i < 2; i++) {
                    mma4(acc[i][j], ah[i], bh);
                    mma4(acc[i][j], ah[i], bl);
                    mma4(acc[i][j], al[i], bh);
                }
            }
        }
        if (c + 1 < 16) sts_chunk((c + 1) & 1);
        __syncthreads();
    }

    // epilogue
#pragma unroll
    for (int i = 0; i < 2; i++)
#pragma unroll
        for (int j = 0; j < 4; j++) {
            long row = tile + wm * 32 + i * 16 + g;
            int col = wn * 32 + j * 8 + 2 * t;
            *(float2*)(out + row * NH + col) =
                make_float2(acc[i][j][0], acc[i][j][1]);
            *(float2*)(out + (row + 8) * NH + col) =
                make_float2(acc[i][j][2], acc[i][j][3]);
        }
}

// ---------------------------------------------------------------------------
// Flash attention (causal) with bf16x2 split mma.sync for QK^T and PV.
// Tq = Tk = 64. block 256 = 8 warps: warp_m = wid&3 (16 rows), warp_n = wid>>2
// (32 cols). Online softmax fully registerized (shfl over 4-lane groups +
// one smem exchange across the 2 warp_n halves). P stored to smem as hi/lo
// pairs directly from the mma accumulator layout.
// grid (16, 8): block handles q-tile pair (i, 31-i) -> balanced 33 steps.
// ---------------------------------------------------------------------------
__global__ __launch_bounds__(256, 1) void attn_kernel(float* __restrict__ out)
{
    extern __shared__ u64 sma[];
    u64* Qs = sma;                  // [64][PSTR]
    u64* Ks = Qs + 64 * PSTR;
    u64* Vt = Ks + 64 * PSTR;       // V^T: [o][s-pair]
    u64* Ps = Vt + 64 * PSTR;
    float* pmax = (float*)(Ps + 64 * PSTR);  // [64][2]
    float* psum = pmax + 128;                // [64][2]

    const int tid = threadIdx.x;
    const int lane = tid & 31, wid = tid >> 5;
    const int g = lane >> 2, t = lane & 3;
    const int wm = wid & 3, wn = wid >> 2;
    const int b = blockIdx.y;
    const int row0 = wm * 16 + g;        // within-tile rows owned by this thread
    const int row1 = row0 + 8;

#pragma unroll 1
    for (int pass = 0; pass < 2; pass++) {
        const int qt = pass ? (31 - (int)blockIdx.x) : (int)blockIdx.x;
        const int qbase = qt * 64;

        // ---- load Q (pre-scaled), split to bf16 pairs ----
        const float* qg = g_q + ((long)b * NT + qbase) * NH;
#pragma unroll
        for (int it = 0; it < 4; it++) {
            int idx = tid + 256 * it;
            int r = idx >> 4, c4 = idx & 15;
            float4 v = *(const float4*)(qg + r * 64 + c4 * 4);
            ulonglong2 st;
            st.x = bsplit2(v.x * 0.125f, v.y * 0.125f);
            st.y = bsplit2(v.z * 0.125f, v.w * 0.125f);
            *reinterpret_cast<ulonglong2*>(&Qs[r * PSTR + 2 * c4]) = st;
        }

        float mr0 = -1e30f, mr1 = -1e30f, lr0 = 0.f, lr1 = 0.f;
        float O[4][4];
#pragma unroll
        for (int j = 0; j < 4; j++)
#pragma unroll
            for (int e = 0; e < 4; e++) O[j][e] = 0.f;
        __syncthreads();

        for (int kt = 0; kt <= qt; kt++) {
            // ---- convert K tile ----
            const float* kg = g_k + ((long)b * NT + kt * 64) * NH;
#pragma unroll
            for (int it = 0; it < 4; it++) {
                int idx = tid + 256 * it;
                int r = idx >> 4, c4 = idx & 15;
                float4 v = *(const float4*)(kg + r * 64 + c4 * 4);
                ulonglong2 st;
                st.x = bsplit2(v.x, v.y);
                st.y = bsplit2(v.z, v.w);
                *reinterpret_cast<ulonglong2*>(&Ks[r * PSTR + 2 * c4]) = st;
            }
            // ---- convert V tile into V^T [o][s-pair] ----
            const float* vg = g_v + ((long)b * NT + kt * 64) * NH;
#pragma unroll
            for (int it = 0; it < 8; it++) {
                int idx2 = wid + 8 * it;             // 0..63
                int o = (idx2 & 7) * 8 + g;
                int sp = (idx2 >> 3) * 4 + t;
                float f0 = vg[(2 * sp) * 64 + o];
                float f1 = vg[(2 * sp + 1) * 64 + o];
                Vt[o * PSTR + sp] = bsplit2(f0, f1);
            }
            __syncthreads();

            // ---- S = Q K^T ----
            float s[4][4];
#pragma unroll
            for (int j = 0; j < 4; j++)
#pragma unroll
                for (int e = 0; e < 4; e++) s[j][e] = 0.f;
#pragma unroll
            for (int ks = 0; ks < 4; ks++) {
                uint32_t ah[4], al[4];
                up2(Qs[row0 * PSTR + 8 * ks + t],     ah[0], al[0]);
                up2(Qs[row1 * PSTR + 8 * ks + t],     ah[1], al[1]);
                up2(Qs[row0 * PSTR + 8 * ks + t + 4], ah[2], al[2]);
                up2(Qs[row1 * PSTR + 8 * ks + t + 4], ah[3], al[3]);
#pragma unroll
                for (int j = 0; j < 4; j++) {
                    int n = wn * 32 + j * 8 + g;
                    uint32_t bh[2], bl[2];
                    up2(Ks[n * PSTR + 8 * ks + t],     bh[0], bl[0]);
                    up2(Ks[n * PSTR + 8 * ks + t + 4], bh[1], bl[1]);
                    mma4(s[j], ah, bh);
                    mma4(s[j], ah, bl);
                    mma4(s[j], al, bh);
                }
            }

            // ---- causal mask on the diagonal tile ----
            if (kt == qt) {
#pragma unroll
                for (int j = 0; j < 4; j++) {
                    int col = wn * 32 + j * 8 + 2 * t;
                    if (col > row0)     s[j][0] = -1e30f;
                    if (col + 1 > row0) s[j][1] = -1e30f;
                    if (col > row1)     s[j][2] = -1e30f;
                    if (col + 1 > row1) s[j][3] = -1e30f;
                }
            }

            // ---- online softmax ----
            float mx0 = -1e30f, mx1 = -1e30f;
#pragma unroll
            for (int j = 0; j < 4; j++) {
                mx0 = fmaxf(mx0, fmaxf(s[j][0], s[j][1]));
                mx1 = fmaxf(mx1, fmaxf(s[j][2], s[j][3]));
            }
            mx0 = fmaxf(mx0, __shfl_xor_sync(0xffffffffu, mx0, 1));
            mx0 = fmaxf(mx0, __shfl_xor_sync(0xffffffffu, mx0, 2));
            mx1 = fmaxf(mx1, __shfl_xor_sync(0xffffffffu, mx1, 1));
            mx1 = fmaxf(mx1, __shfl_xor_sync(0xffffffffu, mx1, 2));
            if (t == 0) {
                pmax[row0 * 2 + wn] = mx0;
                pmax[row1 * 2 + wn] = mx1;
            }
            __syncthreads();
            float M0 = fmaxf(pmax[row0 * 2], pmax[row0 * 2 + 1]);
            float M1 = fmaxf(pmax[row1 * 2], pmax[row1 * 2 + 1]);
            float mn0 = fmaxf(mr0, M0), mn1 = fmaxf(mr1, M1);
            float f0 = __expf(mr0 - mn0), f1 = __expf(mr1 - mn1);
            mr0 = mn0; mr1 = mn1;

            float sum0 = 0.f, sum1 = 0.f;
#pragma unroll
            for (int j = 0; j < 4; j++) {
                float p0 = __expf(s[j][0] - mn0);
                float p1 = __expf(s[j][1] - mn0);
                float p2 = __expf(s[j][2] - mn1);
                float p3 = __expf(s[j][3] - mn1);
                sum0 += p0 + p1;
                sum1 += p2 + p3;
                int sp = wn * 16 + j * 4 + t;
                Ps[row0 * PSTR + sp] = bsplit2(p0, p1);
                Ps[row1 * PSTR + sp] = bsplit2(p2, p3);
                O[j][0] *= f0; O[j][1] *= f0;
                O[j][2] *= f1; O[j][3] *= f1;
            }
            sum0 += __shfl_xor_sync(0xffffffffu, sum0, 1);
            sum0 += __shfl_xor_sync(0xffffffffu, sum0, 2);
            sum1 += __shfl_xor_sync(0xffffffffu, sum1, 1);
            sum1 += __shfl_xor_sync(0xffffffffu, sum1, 2);
            lr0 = lr0 * f0 + sum0;
            lr1 = lr1 * f1 + sum1;
            __syncthreads();   // P visible to all warps

            // ---- O += P V ----
#pragma unroll
            for (int ks = 0; ks < 4; ks++) {
                uint32_t ah[4], al[4];
                up2(Ps[row0 * PSTR + 8 * ks + t],     ah[0], al[0]);
                up2(Ps[row1 * PSTR + 8 * ks + t],     ah[1], al[1]);
                up2(Ps[row0 * PSTR + 8 * ks + t + 4], ah[2], al[2]);
                up2(Ps[row1 * PSTR + 8 * ks + t + 4], ah[3], al[3]);
#pragma unroll
                for (int j = 0; j < 4; j++) {
                    int n = wn * 32 + j * 8 + g;
                    uint32_t bh[2], bl[2];
                    up2(Vt[n * PSTR + 8 * ks + t],     bh[0], bl[0]);
                    up2(Vt[n * PSTR + 8 * ks + t + 4], bh[1], bl[1]);
                    mma4(O[j], ah, bh);
                    mma4(O[j], ah, bl);
                    mma4(O[j], al, bh);
                }
            }
            __syncthreads();   // done reading K/V/P before next tile overwrites
        }

        // ---- epilogue ----
        if (t == 0) {
            psum[row0 * 2 + wn] = lr0;
            psum[row1 * 2 + wn] = lr1;
        }
        __syncthreads();
        float inv0 = 1.0f / (psum[row0 * 2] + psum[row0 * 2 + 1]);
        float inv1 = 1.0f / (psum[row1 * 2] + psum[row1 * 2 + 1]);
#pragma unroll
        for (int j = 0; j < 4; j++) {
            int col = wn * 32 + j * 8 + 2 * t;
            *(float2*)(out + ((long)b * NT + qbase + row0) * NH + col) =
                make_float2(O[j][0] * inv0, O[j][1] * inv0);
            *(float2*)(out + ((long)b * NT + qbase + row1) * NH + col) =
                make_float2(O[j][2] * inv1, O[j][3] * inv1);
        }
        __syncthreads();
    }
}

extern "C" void kernel_launch(void* const* d_in, const int* in_sizes, int n_in,
                              void* d_out, int out_size)
{
    const float* x  = (const float*)d_in[0];
    const float* Wk = (const float*)d_in[1];
    const float* Wq = (const float*)d_in[2];
    const float* Wv = (const float*)d_in[3];
    float* out = (float*)d_out;

    const int proj_smem = (2 * 128 * PSTR + 2 * 64 * PSTR) * 8;   // 110592
    cudaFuncSetAttribute(proj_kernel,
                         cudaFuncAttributeMaxDynamicSharedMemorySize, proj_smem);
    proj_kernel<<<dim3(128, 3), 256, proj_smem>>>(x, Wk, Wq, Wv);

    const int attn_smem = 4 * 64 * PSTR * 8 + 256 * 4;            // 74752
    cudaFuncSetAttribute(attn_kernel,
                         cudaFuncAttributeMaxDynamicSharedMemorySize, attn_smem);
    attn_kernel<<<dim3(16, 8), 256, attn_smem>>>(out);
}

// round 6
// speedup vs baseline: 1.2326x; 1.2326x over previous
#include <cuda_runtime.h>
#include <cuda_bf16.h>
#include <cstdint>

#define NB 8
#define NT 2048
#define NC 1024
#define NH 64
#define NR (NB*NT)
#define SCALE_Q 0.18033688011112042f  // 0.125 * log2(e)

typedef uint32_t u32;

// bf16 hi/lo split planes (device globals: allocation-free rule)
__device__ u32 g_xh[NR*NC/2], g_xl[NR*NC/2];
__device__ u32 g_wh[192*NC/2], g_wl[192*NC/2];
__device__ u32 g_qh[NR*NH/2], g_ql[NR*NH/2];
__device__ u32 g_kh[NR*NH/2], g_kl[NR*NH/2];
__device__ u32 g_vh[NR*NH/2], g_vl[NR*NH/2];

// ---------------- helpers ----------------
__device__ __forceinline__ u32 s2u(const void* p){
    u32 a; asm("{ .reg .u64 t; cvta.to.shared.u64 t, %1; cvt.u32.u64 %0, t; }":"=r"(a):"l"(p)); return a;
}
__device__ __forceinline__ void ldsm4(u32* r, u32 a){
    asm volatile("ldmatrix.sync.aligned.m8n8.x4.shared.b16 {%0,%1,%2,%3},[%4];"
                 :"=r"(r[0]),"=r"(r[1]),"=r"(r[2]),"=r"(r[3]):"r"(a));
}
__device__ __forceinline__ void ldsm4t(u32* r, u32 a){
    asm volatile("ldmatrix.sync.aligned.m8n8.x4.trans.shared.b16 {%0,%1,%2,%3},[%4];"
                 :"=r"(r[0]),"=r"(r[1]),"=r"(r[2]),"=r"(r[3]):"r"(a));
}
__device__ __forceinline__ void mma4(float* c, const u32* a, const u32* b){
    asm volatile("mma.sync.aligned.m16n8k16.row.col.f32.bf16.bf16.f32 "
                 "{%0,%1,%2,%3},{%4,%5,%6,%7},{%8,%9},{%0,%1,%2,%3};"
                 :"+f"(c[0]),"+f"(c[1]),"+f"(c[2]),"+f"(c[3])
                 :"r"(a[0]),"r"(a[1]),"r"(a[2]),"r"(a[3]),"r"(b[0]),"r"(b[1]));
}
__device__ __forceinline__ float ex2f(float x){
    float y; asm("ex2.approx.ftz.f32 %0,%1;":"=f"(y):"f"(x)); return y;
}
__device__ __forceinline__ void cpa(u32 d, const void* s){
    asm volatile("cp.async.cg.shared.global [%0],[%1],16;"::"r"(d),"l"(s));
}
#define CPC asm volatile("cp.async.commit_group;")
#define CPW asm volatile("cp.async.wait_group 0;")
__device__ __forceinline__ u32 bits(__nv_bfloat162 v){ return *reinterpret_cast<u32*>(&v); }
__device__ __forceinline__ void split2(float x, float y, u32& h, u32& l){
    __nv_bfloat162 hh = __floats2bfloat162_rn(x, y);
    float2 hf = __bfloat1622float2(hh);
    h = bits(hh);
    l = bits(__floats2bfloat162_rn(x - hf.x, y - hf.y));
}
__device__ __forceinline__ void split8(float4 a, float4 b, uint4& h, uint4& l){
    split2(a.x, a.y, h.x, l.x); split2(a.z, a.w, h.y, l.y);
    split2(b.x, b.y, h.z, l.z); split2(b.z, b.w, h.w, l.w);
}

// ---------------------------------------------------------------------------
// prep: split x and combined W into bf16 hi/lo planes (once).
// ---------------------------------------------------------------------------
__global__ __launch_bounds__(256) void prep_kernel(
    const float* __restrict__ x, const float* __restrict__ Wk,
    const float* __restrict__ Wq, const float* __restrict__ Wv)
{
    const long xitems = (long)NR * NC / 8;               // 2097152
    long i = (long)blockIdx.x * 256 + threadIdx.x;
    if (i < xitems) {
        const float4* p = (const float4*)x + 2 * i;
        uint4 h, l; split8(p[0], p[1], h, l);
        ((uint4*)g_xh)[i] = h; ((uint4*)g_xl)[i] = l;
    } else {
        long wi = i - xitems;
        if (wi < 192 * NC / 8) {
            int r = (int)(wi >> 7), c8 = (int)(wi & 127);
            const float* Wp = (r < 64)  ? Wk + (long)r * NC
                            : (r < 128) ? Wq + (long)(r - 64) * NC
                                        : Wv + (long)(r - 128) * NC;
            uint4 h, l;
            split8(*(const float4*)(Wp + c8 * 8), *(const float4*)(Wp + c8 * 8 + 4), h, l);
            ((uint4*)g_wh)[wi] = h; ((uint4*)g_wl)[wi] = l;
        }
    }
}

// ---------------------------------------------------------------------------
// proj: out[16384,192] = x * [Wk;Wq;Wv]^T. grid 128, block 512 (16 warps 4x4).
// Warp tile 32 rows x 48 cols. K chunks of 64, cp.async double buffered,
// ldmatrix fragments from swizzled planes. Epilogue -> split q/k/v planes.
// ---------------------------------------------------------------------------
#define PA(b,p) ((b)*32768 + (p)*16384)
#define PB(b,p) (65536 + (b)*49152 + (p)*24576)
#define PSM 163840

__global__ __launch_bounds__(512) void proj_kernel()
{
    extern __shared__ char sm[];
    const u32 sb = s2u(sm);
    const int tid = threadIdx.x, lane = tid & 31, wid = tid >> 5;
    const int g = lane >> 2, t = lane & 3;
    const int l7 = lane & 7, b3 = (lane >> 3) & 1, h16 = lane >> 4;
    const int wm = wid & 3, wn = wid >> 2;
    const long tile = (long)blockIdx.x * 128;

    auto cpch = [&](int c, int buf) {
        const uint4* xs[2] = {(const uint4*)g_xh, (const uint4*)g_xl};
        const uint4* ws[2] = {(const uint4*)g_wh, (const uint4*)g_wl};
#pragma unroll
        for (int pl = 0; pl < 2; pl++) {
#pragma unroll
            for (int it = 0; it < 2; it++) {
                int idx = tid + 512 * it, r = idx >> 3, gr = idx & 7;
                cpa(sb + PA(buf,pl) + r*128 + ((gr^(r&7))<<4),
                    xs[pl] + (tile + r)*128 + c*8 + gr);
            }
#pragma unroll
            for (int it = 0; it < 3; it++) {
                int idx = tid + 512 * it, r = idx >> 3, gr = idx & 7;
                cpa(sb + PB(buf,pl) + r*128 + ((gr^(r&7))<<4),
                    ws[pl] + (long)r*128 + c*8 + gr);
            }
        }
    };

    float acc[2][6][4];
#pragma unroll
    for (int i = 0; i < 2; i++)
#pragma unroll
        for (int j = 0; j < 6; j++)
#pragma unroll
            for (int e = 0; e < 4; e++) acc[i][j][e] = 0.f;

    cpch(0, 0); CPC; CPW; __syncthreads();

    for (int c = 0; c < 16; c++) {
        if (c < 15) { cpch(c + 1, (c + 1) & 1); CPC; }
        const u32 Ah = sb + PA(c&1,0), Al = sb + PA(c&1,1);
        const u32 Bh = sb + PB(c&1,0), Bl = sb + PB(c&1,1);
#pragma unroll
        for (int ks = 0; ks < 4; ks++) {
            u32 ah[2][4], al[2][4];
#pragma unroll
            for (int i = 0; i < 2; i++) {
                u32 off = (u32)((32*wm + 16*i + b3*8 + l7)*128 + (((2*ks + h16) ^ l7) << 4));
                ldsm4(ah[i], Ah + off); ldsm4(al[i], Al + off);
            }
#pragma unroll
            for (int jp = 0; jp < 3; jp++) {
                u32 off = (u32)((48*wn + (2*jp + h16)*8 + l7)*128 + (((2*ks + b3) ^ l7) << 4));
                u32 bh[4], bl[4];
                ldsm4(bh, Bh + off); ldsm4(bl, Bl + off);
#pragma unroll
                for (int i = 0; i < 2; i++) {
                    mma4(acc[i][2*jp],   ah[i], bh);   mma4(acc[i][2*jp],   ah[i], bl);
                    mma4(acc[i][2*jp],   al[i], bh);
                    mma4(acc[i][2*jp+1], ah[i], bh+2); mma4(acc[i][2*jp+1], ah[i], bl+2);
                    mma4(acc[i][2*jp+1], al[i], bh+2);
                }
            }
        }
        CPW; __syncthreads();
    }

#pragma unroll
    for (int i = 0; i < 2; i++)
#pragma unroll
        for (int j = 0; j < 6; j++) {
            int colg = 48*wn + 8*j + 2*t;
            int tn = colg >> 6, col = colg & 63;
            float sc = (tn == 1) ? SCALE_Q : 1.f;
            u32* hp = (tn == 0) ? g_kh : (tn == 1) ? g_qh : g_vh;
            u32* lp = (tn == 0) ? g_kl : (tn == 1) ? g_ql : g_vl;
            long r0 = tile + 32*wm + 16*i + g;
            u32 h, l;
            split2(acc[i][j][0]*sc, acc[i][j][1]*sc, h, l);
            hp[(r0*64 + col) >> 1] = h; lp[(r0*64 + col) >> 1] = l;
            split2(acc[i][j][2]*sc, acc[i][j][3]*sc, h, l);
            hp[((r0+8)*64 + col) >> 1] = h; lp[((r0+8)*64 + col) >> 1] = l;
        }
}

// ---------------------------------------------------------------------------
// attn: causal flash, Tq=128, Tk=64. block 256 = 8 warps; warp owns 16 rows x
// 64 cols -> warp-local softmax, P stays in registers (S accum -> PV A-frags).
// K/V cp.async double buffered, 1 barrier/step. grid (16 qt, 8 b).
// ---------------------------------------------------------------------------
#define AQ(p)   ((p)*16384)
#define AK(b,p) (32768 + (b)*16384 + (p)*8192)
#define AV(b,p) (65536 + (b)*16384 + (p)*8192)
#define ASM 98304

__global__ __launch_bounds__(256) void attn_kernel(float* __restrict__ out)
{
    extern __shared__ char sm[];
    const u32 sb = s2u(sm);
    const int tid = threadIdx.x, lane = tid & 31, w = tid >> 5;
    const int g = lane >> 2, t = lane & 3;
    const int l7 = lane & 7, b3 = (lane >> 3) & 1, h16 = lane >> 4;
    const int qt = blockIdx.x, b = blockIdx.y;
    const int ktmax = 2*qt + 1;
    const long qrow0 = (long)b*NT + qt*128;

    auto cpkv = [&](int kt, int buf) {
        long rb = (long)b*NT + kt*64;
        const uint4* srcs[4] = {(const uint4*)g_kh, (const uint4*)g_kl,
                                (const uint4*)g_vh, (const uint4*)g_vl};
        u32 dsts[4] = {sb+AK(buf,0), sb+AK(buf,1), sb+AV(buf,0), sb+AV(buf,1)};
#pragma unroll
        for (int p = 0; p < 4; p++)
#pragma unroll
            for (int it = 0; it < 2; it++) {
                int idx = tid + 256*it, r = idx >> 3, gr = idx & 7;
                cpa(dsts[p] + r*128 + ((gr^(r&7))<<4), srcs[p] + (rb + r)*8 + gr);
            }
    };

    {   // Q planes + first K/V
        const uint4* qs[2] = {(const uint4*)g_qh, (const uint4*)g_ql};
#pragma unroll
        for (int p = 0; p < 2; p++)
#pragma unroll
            for (int it = 0; it < 4; it++) {
                int idx = tid + 256*it, r = idx >> 3, gr = idx & 7;
                cpa(sb + AQ(p) + r*128 + ((gr^(r&7))<<4), qs[p] + (qrow0 + r)*8 + gr);
            }
        cpkv(0, 0); CPC; CPW; __syncthreads();
    }

    u32 qh[4][4], ql[4][4];
#pragma unroll
    for (int ks = 0; ks < 4; ks++) {
        u32 off = (u32)((16*w + b3*8 + l7)*128 + (((2*ks + h16) ^ l7) << 4));
        ldsm4(qh[ks], sb + AQ(0) + off);
        ldsm4(ql[ks], sb + AQ(1) + off);
    }

    float O[8][4];
#pragma unroll
    for (int j = 0; j < 8; j++)
#pragma unroll
        for (int e = 0; e < 4; e++) O[j][e] = 0.f;
    float m0 = -1e30f, m1 = -1e30f, L0 = 0.f, L1 = 0.f;
    const int rfirst = qt*128 + 16*w;

    for (int kt = 0; kt <= ktmax; kt++) {
        int buf = kt & 1;
        if (kt < ktmax) { cpkv(kt + 1, buf ^ 1); CPC; }

        if (kt*64 <= rfirst + 15) {
            const u32 KH = sb+AK(buf,0), KL = sb+AK(buf,1);
            const u32 VH = sb+AV(buf,0), VL = sb+AV(buf,1);
            float s[8][4];
#pragma unroll
            for (int j = 0; j < 8; j++)
#pragma unroll
                for (int e = 0; e < 4; e++) s[j][e] = 0.f;

#pragma unroll
            for (int ks = 0; ks < 4; ks++)
#pragma unroll
                for (int jp = 0; jp < 4; jp++) {
                    u32 off = (u32)(((2*jp + h16)*8 + l7)*128 + (((2*ks + b3) ^ l7) << 4));
                    u32 bh[4], bl[4];
                    ldsm4(bh, KH + off); ldsm4(bl, KL + off);
                    mma4(s[2*jp],   qh[ks], bh);   mma4(s[2*jp],   qh[ks], bl);
                    mma4(s[2*jp],   ql[ks], bh);
                    mma4(s[2*jp+1], qh[ks], bh+2); mma4(s[2*jp+1], qh[ks], bl+2);
                    mma4(s[2*jp+1], ql[ks], bh+2);
                }

            if (kt*64 + 63 > rfirst) {
                int r0g = rfirst + g, r1g = r0g + 8;
#pragma unroll
                for (int j = 0; j < 8; j++) {
                    int cg = kt*64 + j*8 + 2*t;
                    if (cg > r0g)     s[j][0] = -1e30f;
                    if (cg + 1 > r0g) s[j][1] = -1e30f;
                    if (cg > r1g)     s[j][2] = -1e30f;
                    if (cg + 1 > r1g) s[j][3] = -1e30f;
                }
            }

            float mx0 = -1e30f, mx1 = -1e30f;
#pragma unroll
            for (int j = 0; j < 8; j++) {
                mx0 = fmaxf(mx0, fmaxf(s[j][0], s[j][1]));
                mx1 = fmaxf(mx1, fmaxf(s[j][2], s[j][3]));
            }
            mx0 = fmaxf(mx0, __shfl_xor_sync(~0u, mx0, 1));
            mx0 = fmaxf(mx0, __shfl_xor_sync(~0u, mx0, 2));
            mx1 = fmaxf(mx1, __shfl_xor_sync(~0u, mx1, 1));
            mx1 = fmaxf(mx1, __shfl_xor_sync(~0u, mx1, 2));
            float mn0 = fmaxf(m0, mx0), mn1 = fmaxf(m1, mx1);
            float f0 = ex2f(m0 - mn0), f1 = ex2f(m1 - mn1);
            m0 = mn0; m1 = mn1;

            float s0 = 0.f, s1 = 0.f;
#pragma unroll
            for (int j = 0; j < 8; j++) {
                s[j][0] = ex2f(s[j][0] - mn0); s[j][1] = ex2f(s[j][1] - mn0);
                s[j][2] = ex2f(s[j][2] - mn1); s[j][3] = ex2f(s[j][3] - mn1);
                s0 += s[j][0] + s[j][1];
                s1 += s[j][2] + s[j][3];
            }
            s0 += __shfl_xor_sync(~0u, s0, 1); s0 += __shfl_xor_sync(~0u, s0, 2);
            s1 += __shfl_xor_sync(~0u, s1, 1); s1 += __shfl_xor_sync(~0u, s1, 2);
            L0 = L0 * f0 + s0; L1 = L1 * f1 + s1;

            u32 ph[4][4], pl2[4][4];
#pragma unroll
            for (int ks = 0; ks < 4; ks++) {
                split2(s[2*ks][0],   s[2*ks][1],   ph[ks][0], pl2[ks][0]);
                split2(s[2*ks][2],   s[2*ks][3],   ph[ks][1], pl2[ks][1]);
                split2(s[2*ks+1][0], s[2*ks+1][1], ph[ks][2], pl2[ks][2]);
                split2(s[2*ks+1][2], s[2*ks+1][3], ph[ks][3], pl2[ks][3]);
            }
#pragma unroll
            for (int j = 0; j < 8; j++) {
                O[j][0] *= f0; O[j][1] *= f0; O[j][2] *= f1; O[j][3] *= f1;
            }

#pragma unroll
            for (int ks = 0; ks < 4; ks++)
#pragma unroll
                for (int jp = 0; jp < 4; jp++) {
                    u32 off = (u32)((16*ks + b3*8 + l7)*128 + (((2*jp + h16) ^ l7) << 4));
                    u32 vh[4], vl[4];
                    ldsm4t(vh, VH + off); ldsm4t(vl, VL + off);
                    mma4(O[2*jp],   ph[ks],  vh);   mma4(O[2*jp],   ph[ks],  vl);
                    mma4(O[2*jp],   pl2[ks], vh);
                    mma4(O[2*jp+1], ph[ks],  vh+2); mma4(O[2*jp+1], ph[ks],  vl+2);
                    mma4(O[2*jp+1], pl2[ks], vh+2);
                }
        }
        CPW; __syncthreads();
    }

    float i0 = 1.f / L0, i1 = 1.f / L1;
#pragma unroll
    for (int j = 0; j < 8; j++) {
        int col = j*8 + 2*t;
        *(float2*)(out + (qrow0 + 16*w + g)*64 + col) =
            make_float2(O[j][0]*i0, O[j][1]*i0);
        *(float2*)(out + (qrow0 + 16*w + g + 8)*64 + col) =
            make_float2(O[j][2]*i1, O[j][3]*i1);
    }
}

extern "C" void kernel_launch(void* const* d_in, const int* in_sizes, int n_in,
                              void* d_out, int out_size)
{
    const float* x  = (const float*)d_in[0];
    const float* Wk = (const float*)d_in[1];
    const float* Wq = (const float*)d_in[2];
    const float* Wv = (const float*)d_in[3];
    float* out = (float*)d_out;

    const long items = (long)NR*NC/8 + 192*NC/8;   // 2121728
    prep_kernel<<<(int)((items + 255) / 256), 256>>>(x, Wk, Wq, Wv);

    cudaFuncSetAttribute(proj_kernel,
                         cudaFuncAttributeMaxDynamicSharedMemorySize, PSM);
    proj_kernel<<<128, 512, PSM>>>();

    cudaFuncSetAttribute(attn_kernel,
                         cudaFuncAttributeMaxDynamicSharedMemorySize, ASM);
    attn_kernel<<<dim3(16, 8), 256, ASM>>>(out);
}

// round 7
// speedup vs baseline: 1.3385x; 1.0860x over previous
#include <cuda_runtime.h>
#include <cuda_bf16.h>
#include <cstdint>

#define NB 8
#define NT 2048
#define NC 1024
#define NH 64
#define NR (NB*NT)
#define SCALE_Q 0.18033688011112042f  // 0.125 * log2(e)

typedef uint32_t u32;

// bf16 hi/lo split planes + split-KV scratch (device globals: allocation-free)
__device__ u32 g_xh[NR*NC/2], g_xl[NR*NC/2];
__device__ u32 g_wh[192*NC/2], g_wl[192*NC/2];
__device__ u32 g_qh[NR*NH/2], g_ql[NR*NH/2];
__device__ u32 g_kh[NR*NH/2], g_kl[NR*NH/2];
__device__ u32 g_vh[NR*NH/2], g_vl[NR*NH/2];
__device__ float g_O0[NR*NH], g_O1[NR*NH];
__device__ float g_m0[NR], g_m1[NR], g_l0[NR], g_l1[NR];

// ---------------- helpers ----------------
__device__ __forceinline__ u32 s2u(const void* p){
    u32 a; asm("{ .reg .u64 t; cvta.to.shared.u64 t, %1; cvt.u32.u64 %0, t; }":"=r"(a):"l"(p)); return a;
}
__device__ __forceinline__ void ldsm4(u32* r, u32 a){
    asm volatile("ldmatrix.sync.aligned.m8n8.x4.shared.b16 {%0,%1,%2,%3},[%4];"
                 :"=r"(r[0]),"=r"(r[1]),"=r"(r[2]),"=r"(r[3]):"r"(a));
}
__device__ __forceinline__ void ldsm4t(u32* r, u32 a){
    asm volatile("ldmatrix.sync.aligned.m8n8.x4.trans.shared.b16 {%0,%1,%2,%3},[%4];"
                 :"=r"(r[0]),"=r"(r[1]),"=r"(r[2]),"=r"(r[3]):"r"(a));
}
__device__ __forceinline__ void mma4(float* c, const u32* a, const u32* b){
    asm volatile("mma.sync.aligned.m16n8k16.row.col.f32.bf16.bf16.f32 "
                 "{%0,%1,%2,%3},{%4,%5,%6,%7},{%8,%9},{%0,%1,%2,%3};"
                 :"+f"(c[0]),"+f"(c[1]),"+f"(c[2]),"+f"(c[3])
                 :"r"(a[0]),"r"(a[1]),"r"(a[2]),"r"(a[3]),"r"(b[0]),"r"(b[1]));
}
__device__ __forceinline__ float ex2f(float x){
    float y; asm("ex2.approx.ftz.f32 %0,%1;":"=f"(y):"f"(x)); return y;
}
__device__ __forceinline__ void cpa(u32 d, const void* s){
    asm volatile("cp.async.cg.shared.global [%0],[%1],16;"::"r"(d),"l"(s));
}
#define CPC asm volatile("cp.async.commit_group;")
#define CPW asm volatile("cp.async.wait_group 0;")
__device__ __forceinline__ u32 bits(__nv_bfloat162 v){ return *reinterpret_cast<u32*>(&v); }
__device__ __forceinline__ void split2(float x, float y, u32& h, u32& l){
    __nv_bfloat162 hh = __floats2bfloat162_rn(x, y);
    float2 hf = __bfloat1622float2(hh);
    h = bits(hh);
    l = bits(__floats2bfloat162_rn(x - hf.x, y - hf.y));
}
__device__ __forceinline__ void split8(float4 a, float4 b, uint4& h, uint4& l){
    split2(a.x, a.y, h.x, l.x); split2(a.z, a.w, h.y, l.y);
    split2(b.x, b.y, h.z, l.z); split2(b.z, b.w, h.w, l.w);
}

// ---------------------------------------------------------------------------
// prep: split x and combined W into bf16 hi/lo planes (once). HBM-roofline.
// ---------------------------------------------------------------------------
__global__ __launch_bounds__(256) void prep_kernel(
    const float* __restrict__ x, const float* __restrict__ Wk,
    const float* __restrict__ Wq, const float* __restrict__ Wv)
{
    const long xitems = (long)NR * NC / 8;
    long i = (long)blockIdx.x * 256 + threadIdx.x;
    if (i < xitems) {
        const float4* p = (const float4*)x + 2 * i;
        uint4 h, l; split8(p[0], p[1], h, l);
        ((uint4*)g_xh)[i] = h; ((uint4*)g_xl)[i] = l;
    } else {
        long wi = i - xitems;
        if (wi < 192 * NC / 8) {
            int r = (int)(wi >> 7), c8 = (int)(wi & 127);
            const float* Wp = (r < 64)  ? Wk + (long)r * NC
                            : (r < 128) ? Wq + (long)(r - 64) * NC
                                        : Wv + (long)(r - 128) * NC;
            uint4 h, l;
            split8(*(const float4*)(Wp + c8 * 8), *(const float4*)(Wp + c8 * 8 + 4), h, l);
            ((uint4*)g_wh)[wi] = h; ((uint4*)g_wl)[wi] = l;
        }
    }
}

// ---------------------------------------------------------------------------
// proj: out[16384,192] = x * [Wk;Wq;Wv]^T. grid 128, block 512 (16 warps 4x4).
// cp.async double buffered, ldmatrix frags, epilogue -> split q/k/v planes.
// ---------------------------------------------------------------------------
#define PA(b,p) ((b)*32768 + (p)*16384)
#define PB(b,p) (65536 + (b)*49152 + (p)*24576)
#define PSM 163840

__global__ __launch_bounds__(512) void proj_kernel()
{
    extern __shared__ char sm[];
    const u32 sb = s2u(sm);
    const int tid = threadIdx.x, lane = tid & 31, wid = tid >> 5;
    const int g = lane >> 2, t = lane & 3;
    const int l7 = lane & 7, b3 = (lane >> 3) & 1, h16 = lane >> 4;
    const int wm = wid & 3, wn = wid >> 2;
    const long tile = (long)blockIdx.x * 128;

    auto cpch = [&](int c, int buf) {
        const uint4* xs[2] = {(const uint4*)g_xh, (const uint4*)g_xl};
        const uint4* ws[2] = {(const uint4*)g_wh, (const uint4*)g_wl};
#pragma unroll
        for (int pl = 0; pl < 2; pl++) {
#pragma unroll
            for (int it = 0; it < 2; it++) {
                int idx = tid + 512 * it, r = idx >> 3, gr = idx & 7;
                cpa(sb + PA(buf,pl) + r*128 + ((gr^(r&7))<<4),
                    xs[pl] + (tile + r)*128 + c*8 + gr);
            }
#pragma unroll
            for (int it = 0; it < 3; it++) {
                int idx = tid + 512 * it, r = idx >> 3, gr = idx & 7;
                cpa(sb + PB(buf,pl) + r*128 + ((gr^(r&7))<<4),
                    ws[pl] + (long)r*128 + c*8 + gr);
            }
        }
    };

    float acc[2][6][4];
#pragma unroll
    for (int i = 0; i < 2; i++)
#pragma unroll
        for (int j = 0; j < 6; j++)
#pragma unroll
            for (int e = 0; e < 4; e++) acc[i][j][e] = 0.f;

    cpch(0, 0); CPC; CPW; __syncthreads();

    for (int c = 0; c < 16; c++) {
        if (c < 15) { cpch(c + 1, (c + 1) & 1); CPC; }
        const u32 Ah = sb + PA(c&1,0), Al = sb + PA(c&1,1);
        const u32 Bh = sb + PB(c&1,0), Bl = sb + PB(c&1,1);
#pragma unroll
        for (int ks = 0; ks < 4; ks++) {
            u32 ah[2][4], al[2][4];
#pragma unroll
            for (int i = 0; i < 2; i++) {
                u32 off = (u32)((32*wm + 16*i + b3*8 + l7)*128 + (((2*ks + h16) ^ l7) << 4));
                ldsm4(ah[i], Ah + off); ldsm4(al[i], Al + off);
            }
#pragma unroll
            for (int jp = 0; jp < 3; jp++) {
                u32 off = (u32)((48*wn + (2*jp + h16)*8 + l7)*128 + (((2*ks + b3) ^ l7) << 4));
                u32 bh[4], bl[4];
                ldsm4(bh, Bh + off); ldsm4(bl, Bl + off);
#pragma unroll
                for (int i = 0; i < 2; i++) {
                    mma4(acc[i][2*jp],   ah[i], bh);   mma4(acc[i][2*jp],   ah[i], bl);
                    mma4(acc[i][2*jp],   al[i], bh);
                    mma4(acc[i][2*jp+1], ah[i], bh+2); mma4(acc[i][2*jp+1], ah[i], bl+2);
                    mma4(acc[i][2*jp+1], al[i], bh+2);
                }
            }
        }
        CPW; __syncthreads();
    }

#pragma unroll
    for (int i = 0; i < 2; i++)
#pragma unroll
        for (int j = 0; j < 6; j++) {
            int colg = 48*wn + 8*j + 2*t;
            int tn = colg >> 6, col = colg & 63;
            float sc = (tn == 1) ? SCALE_Q : 1.f;
            u32* hp = (tn == 0) ? g_kh : (tn == 1) ? g_qh : g_vh;
            u32* lp = (tn == 0) ? g_kl : (tn == 1) ? g_ql : g_vl;
            long r0 = tile + 32*wm + 16*i + g;
            u32 h, l;
            split2(acc[i][j][0]*sc, acc[i][j][1]*sc, h, l);
            hp[(r0*64 + col) >> 1] = h; lp[(r0*64 + col) >> 1] = l;
            split2(acc[i][j][2]*sc, acc[i][j][3]*sc, h, l);
            hp[((r0+8)*64 + col) >> 1] = h; lp[((r0+8)*64 + col) >> 1] = l;
        }
}

// ---------------------------------------------------------------------------
// attn (split-KV): grid (16 qt, 8 b, 2 z). z=0 -> kv tiles [0..qt],
// z=1 -> [qt+1..2qt+1]; each block qt+1 steps (makespan 16, was 32).
// Warp owns 16 rows x 64 cols, warp-local softmax (log2 domain), P in regs.
// Partials (unnormalized O, m, l) -> global scratch; combine merges.
// ---------------------------------------------------------------------------
#define AQ(p)   ((p)*16384)
#define AK(b,p) (32768 + (b)*16384 + (p)*8192)
#define AV(b,p) (65536 + (b)*16384 + (p)*8192)
#define ASM 98304

__global__ __launch_bounds__(256) void attn_kernel()
{
    extern __shared__ char sm[];
    const u32 sb = s2u(sm);
    const int tid = threadIdx.x, lane = tid & 31, w = tid >> 5;
    const int g = lane >> 2, t = lane & 3;
    const int l7 = lane & 7, b3 = (lane >> 3) & 1, h16 = lane >> 4;
    const int qt = blockIdx.x, b = blockIdx.y, z = blockIdx.z;
    const int kt0 = z ? (qt + 1) : 0;
    const int kt1 = z ? (2*qt + 1) : qt;
    const long qrow0 = (long)b*NT + qt*128;

    auto cpkv = [&](int kt, int buf) {
        long rb = (long)b*NT + kt*64;
        const uint4* srcs[4] = {(const uint4*)g_kh, (const uint4*)g_kl,
                                (const uint4*)g_vh, (const uint4*)g_vl};
        u32 dsts[4] = {sb+AK(buf,0), sb+AK(buf,1), sb+AV(buf,0), sb+AV(buf,1)};
#pragma unroll
        for (int p = 0; p < 4; p++)
#pragma unroll
            for (int it = 0; it < 2; it++) {
                int idx = tid + 256*it, r = idx >> 3, gr = idx & 7;
                cpa(dsts[p] + r*128 + ((gr^(r&7))<<4), srcs[p] + (rb + r)*8 + gr);
            }
    };

    {   // Q planes + first K/V
        const uint4* qs[2] = {(const uint4*)g_qh, (const uint4*)g_ql};
#pragma unroll
        for (int p = 0; p < 2; p++)
#pragma unroll
            for (int it = 0; it < 4; it++) {
                int idx = tid + 256*it, r = idx >> 3, gr = idx & 7;
                cpa(sb + AQ(p) + r*128 + ((gr^(r&7))<<4), qs[p] + (qrow0 + r)*8 + gr);
            }
        cpkv(kt0, 0); CPC; CPW; __syncthreads();
    }

    u32 qh[4][4], ql[4][4];
#pragma unroll
    for (int ks = 0; ks < 4; ks++) {
        u32 off = (u32)((16*w + b3*8 + l7)*128 + (((2*ks + h16) ^ l7) << 4));
        ldsm4(qh[ks], sb + AQ(0) + off);
        ldsm4(ql[ks], sb + AQ(1) + off);
    }

    float O[8][4];
#pragma unroll
    for (int j = 0; j < 8; j++)
#pragma unroll
        for (int e = 0; e < 4; e++) O[j][e] = 0.f;
    float m0 = -1e30f, m1 = -1e30f, L0 = 0.f, L1 = 0.f;
    const int rfirst = qt*128 + 16*w;

    for (int kt = kt0; kt <= kt1; kt++) {
        int buf = (kt - kt0) & 1;
        if (kt < kt1) { cpkv(kt + 1, buf ^ 1); CPC; }

        if (kt*64 <= rfirst + 15) {
            const u32 KH = sb+AK(buf,0), KL = sb+AK(buf,1);
            const u32 VH = sb+AV(buf,0), VL = sb+AV(buf,1);
            float s[8][4];
#pragma unroll
            for (int j = 0; j < 8; j++)
#pragma unroll
                for (int e = 0; e < 4; e++) s[j][e] = 0.f;

#pragma unroll
            for (int ks = 0; ks < 4; ks++)
#pragma unroll
                for (int jp = 0; jp < 4; jp++) {
                    u32 off = (u32)(((2*jp + h16)*8 + l7)*128 + (((2*ks + b3) ^ l7) << 4));
                    u32 bh[4], bl[4];
                    ldsm4(bh, KH + off); ldsm4(bl, KL + off);
                    mma4(s[2*jp],   qh[ks], bh);   mma4(s[2*jp],   qh[ks], bl);
                    mma4(s[2*jp],   ql[ks], bh);
                    mma4(s[2*jp+1], qh[ks], bh+2); mma4(s[2*jp+1], qh[ks], bl+2);
                    mma4(s[2*jp+1], ql[ks], bh+2);
                }

            if (kt*64 + 63 > rfirst) {
                int r0g = rfirst + g, r1g = r0g + 8;
#pragma unroll
                for (int j = 0; j < 8; j++) {
                    int cg = kt*64 + j*8 + 2*t;
                    if (cg > r0g)     s[j][0] = -1e30f;
                    if (cg + 1 > r0g) s[j][1] = -1e30f;
                    if (cg > r1g)     s[j][2] = -1e30f;
                    if (cg + 1 > r1g) s[j][3] = -1e30f;
                }
            }

            float mx0 = -1e30f, mx1 = -1e30f;
#pragma unroll
            for (int j = 0; j < 8; j++) {
                mx0 = fmaxf(mx0, fmaxf(s[j][0], s[j][1]));
                mx1 = fmaxf(mx1, fmaxf(s[j][2], s[j][3]));
            }
            mx0 = fmaxf(mx0, __shfl_xor_sync(~0u, mx0, 1));
            mx0 = fmaxf(mx0, __shfl_xor_sync(~0u, mx0, 2));
            mx1 = fmaxf(mx1, __shfl_xor_sync(~0u, mx1, 1));
            mx1 = fmaxf(mx1, __shfl_xor_sync(~0u, mx1, 2));
            float mn0 = fmaxf(m0, mx0), mn1 = fmaxf(m1, mx1);
            float f0 = ex2f(m0 - mn0), f1 = ex2f(m1 - mn1);
            m0 = mn0; m1 = mn1;

            float s0 = 0.f, s1 = 0.f;
#pragma unroll
            for (int j = 0; j < 8; j++) {
                s[j][0] = ex2f(s[j][0] - mn0); s[j][1] = ex2f(s[j][1] - mn0);
                s[j][2] = ex2f(s[j][2] - mn1); s[j][3] = ex2f(s[j][3] - mn1);
                s0 += s[j][0] + s[j][1];
                s1 += s[j][2] + s[j][3];
            }
            s0 += __shfl_xor_sync(~0u, s0, 1); s0 += __shfl_xor_sync(~0u, s0, 2);
            s1 += __shfl_xor_sync(~0u, s1, 1); s1 += __shfl_xor_sync(~0u, s1, 2);
            L0 = L0 * f0 + s0; L1 = L1 * f1 + s1;

            u32 ph[4][4], pl2[4][4];
#pragma unroll
            for (int ks = 0; ks < 4; ks++) {
                split2(s[2*ks][0],   s[2*ks][1],   ph[ks][0], pl2[ks][0]);
                split2(s[2*ks][2],   s[2*ks][3],   ph[ks][1], pl2[ks][1]);
                split2(s[2*ks+1][0], s[2*ks+1][1], ph[ks][2], pl2[ks][2]);
                split2(s[2*ks+1][2], s[2*ks+1][3], ph[ks][3], pl2[ks][3]);
            }
#pragma unroll
            for (int j = 0; j < 8; j++) {
                O[j][0] *= f0; O[j][1] *= f0; O[j][2] *= f1; O[j][3] *= f1;
            }

#pragma unroll
            for (int ks = 0; ks < 4; ks++)
#pragma unroll
                for (int jp = 0; jp < 4; jp++) {
                    u32 off = (u32)((16*ks + b3*8 + l7)*128 + (((2*jp + h16) ^ l7) << 4));
                    u32 vh[4], vl[4];
                    ldsm4t(vh, VH + off); ldsm4t(vl, VL + off);
                    mma4(O[2*jp],   ph[ks],  vh);   mma4(O[2*jp],   ph[ks],  vl);
                    mma4(O[2*jp],   pl2[ks], vh);
                    mma4(O[2*jp+1], ph[ks],  vh+2); mma4(O[2*jp+1], ph[ks],  vl+2);
                    mma4(O[2*jp+1], pl2[ks], vh+2);
                }
        }
        CPW; __syncthreads();
    }

    // write partials (unnormalized O + m, l)
    float* Od = z ? g_O1 : g_O0;
#pragma unroll
    for (int j = 0; j < 8; j++) {
        int col = j*8 + 2*t;
        *(float2*)(Od + (qrow0 + 16*w + g)*64 + col)     = make_float2(O[j][0], O[j][1]);
        *(float2*)(Od + (qrow0 + 16*w + g + 8)*64 + col) = make_float2(O[j][2], O[j][3]);
    }
    if (t == 0) {
        float* mp = z ? g_m1 : g_m0;
        float* lp = z ? g_l1 : g_l0;
        mp[qrow0 + 16*w + g]     = m0;  lp[qrow0 + 16*w + g]     = L0;
        mp[qrow0 + 16*w + g + 8] = m1;  lp[qrow0 + 16*w + g + 8] = L1;
    }
}

// ---------------------------------------------------------------------------
// combine: out = (O0*2^(m0-M) + O1*2^(m1-M)) / (l0*2^(m0-M) + l1*2^(m1-M))
// ---------------------------------------------------------------------------
__global__ __launch_bounds__(256) void combine_kernel(float* __restrict__ out)
{
    long i = (long)blockIdx.x * 256 + threadIdx.x;   // over NR*16 float4 groups
    long row = i >> 4;
    float mA = g_m0[row], mB = g_m1[row];
    float M = fmaxf(mA, mB);
    float wA = ex2f(mA - M), wB = ex2f(mB - M);
    float inv = 1.f / (g_l0[row] * wA + g_l1[row] * wB);
    float4 a = ((const float4*)g_O0)[i];
    float4 c = ((const float4*)g_O1)[i];
    float4 o;
    o.x = (a.x * wA + c.x * wB) * inv;
    o.y = (a.y * wA + c.y * wB) * inv;
    o.z = (a.z * wA + c.z * wB) * inv;
    o.w = (a.w * wA + c.w * wB) * inv;
    ((float4*)out)[i] = o;
}

extern "C" void kernel_launch(void* const* d_in, const int* in_sizes, int n_in,
                              void* d_out, int out_size)
{
    const float* x  = (const float*)d_in[0];
    const float* Wk = (const float*)d_in[1];
    const float* Wq = (const float*)d_in[2];
    const float* Wv = (const float*)d_in[3];
    float* out = (float*)d_out;

    const long items = (long)NR*NC/8 + 192*NC/8;
    prep_kernel<<<(int)((items + 255) / 256), 256>>>(x, Wk, Wq, Wv);

    cudaFuncSetAttribute(proj_kernel,
                         cudaFuncAttributeMaxDynamicSharedMemorySize, PSM);
    proj_kernel<<<128, 512, PSM>>>();

    cudaFuncSetAttribute(attn_kernel,
                         cudaFuncAttributeMaxDynamicSharedMemorySize, ASM);
    attn_kernel<<<dim3(16, 8, 2), 256, ASM>>>();

    combine_kernel<<<NR * 16 / 256, 256>>>(out);
}

// round 8
// speedup vs baseline: 1.4202x; 1.0610x over previous
#include <cuda_runtime.h>
#include <cuda_bf16.h>
#include <cstdint>

#define NB 8
#define NT 2048
#define NC 1024
#define NH 64
#define NR (NB*NT)
#define SCALE_Q 0.18033688011112042f  // 0.125 * log2(e)

typedef uint32_t u32;

// bf16 hi/lo split planes + split-KV scratch (device globals: allocation-free)
__device__ u32 g_wh[192*NC/2], g_wl[192*NC/2];
__device__ u32 g_qh[NR*NH/2], g_ql[NR*NH/2];
__device__ u32 g_kh[NR*NH/2], g_kl[NR*NH/2];
__device__ u32 g_vh[NR*NH/2], g_vl[NR*NH/2];
__device__ float g_O0[NR*NH], g_O1[NR*NH];
__device__ float g_m0[NR], g_m1[NR], g_l0[NR], g_l1[NR];

// ---------------- helpers ----------------
__device__ __forceinline__ u32 s2u(const void* p){
    u32 a; asm("{ .reg .u64 t; cvta.to.shared.u64 t, %1; cvt.u32.u64 %0, t; }":"=r"(a):"l"(p)); return a;
}
__device__ __forceinline__ void ldsm4(u32* r, u32 a){
    asm volatile("ldmatrix.sync.aligned.m8n8.x4.shared.b16 {%0,%1,%2,%3},[%4];"
                 :"=r"(r[0]),"=r"(r[1]),"=r"(r[2]),"=r"(r[3]):"r"(a));
}
__device__ __forceinline__ void ldsm4t(u32* r, u32 a){
    asm volatile("ldmatrix.sync.aligned.m8n8.x4.trans.shared.b16 {%0,%1,%2,%3},[%4];"
                 :"=r"(r[0]),"=r"(r[1]),"=r"(r[2]),"=r"(r[3]):"r"(a));
}
__device__ __forceinline__ void mma4(float* c, const u32* a, const u32* b){
    asm volatile("mma.sync.aligned.m16n8k16.row.col.f32.bf16.bf16.f32 "
                 "{%0,%1,%2,%3},{%4,%5,%6,%7},{%8,%9},{%0,%1,%2,%3};"
                 :"+f"(c[0]),"+f"(c[1]),"+f"(c[2]),"+f"(c[3])
                 :"r"(a[0]),"r"(a[1]),"r"(a[2]),"r"(a[3]),"r"(b[0]),"r"(b[1]));
}
__device__ __forceinline__ float ex2f(float x){
    float y; asm("ex2.approx.ftz.f32 %0,%1;":"=f"(y):"f"(x)); return y;
}
__device__ __forceinline__ void cpa(u32 d, const void* s){
    asm volatile("cp.async.cg.shared.global [%0],[%1],16;"::"r"(d),"l"(s));
}
#define CPC asm volatile("cp.async.commit_group;")
#define CPW asm volatile("cp.async.wait_group 0;")
__device__ __forceinline__ u32 bits(__nv_bfloat162 v){ return *reinterpret_cast<u32*>(&v); }
__device__ __forceinline__ void split2(float x, float y, u32& h, u32& l){
    __nv_bfloat162 hh = __floats2bfloat162_rn(x, y);
    float2 hf = __bfloat1622float2(hh);
    h = bits(hh);
    l = bits(__floats2bfloat162_rn(x - hf.x, y - hf.y));
}
__device__ __forceinline__ void split8(float4 a, float4 b, uint4& h, uint4& l){
    split2(a.x, a.y, h.x, l.x); split2(a.z, a.w, h.y, l.y);
    split2(b.x, b.y, h.z, l.z); split2(b.z, b.w, h.w, l.w);
}

// ---------------------------------------------------------------------------
// prepW: split combined [Wk;Wq;Wv] into bf16 hi/lo planes (1.5 MB, ~2 us).
// ---------------------------------------------------------------------------
__global__ __launch_bounds__(256) void prepw_kernel(
    const float* __restrict__ Wk, const float* __restrict__ Wq,
    const float* __restrict__ Wv)
{
    long wi = (long)blockIdx.x * 256 + threadIdx.x;
    if (wi < 192 * NC / 8) {
        int r = (int)(wi >> 7), c8 = (int)(wi & 127);
        const float* Wp = (r < 64)  ? Wk + (long)r * NC
                        : (r < 128) ? Wq + (long)(r - 64) * NC
                                    : Wv + (long)(r - 128) * NC;
        uint4 h, l;
        split8(*(const float4*)(Wp + c8 * 8), *(const float4*)(Wp + c8 * 8 + 4), h, l);
        ((uint4*)g_wh)[wi] = h; ((uint4*)g_wl)[wi] = l;
    }
}

// ---------------------------------------------------------------------------
// proj: out[16384,192] = x * [Wk;Wq;Wv]^T. grid 128, block 512 (16 warps 4x4).
// x loaded fp32 via LDG->regs, split in-register, STS to swizzled planes
// (kills the prep x round-trip). W planes via cp.async. Double buffered.
// Epilogue -> split q/k/v planes (q pre-scaled by 0.125*log2e).
// ---------------------------------------------------------------------------
#define PA(b,p) ((b)*32768 + (p)*16384)
#define PB(b,p) (65536 + (b)*49152 + (p)*24576)
#define PSM 163840

__global__ __launch_bounds__(512) void proj_kernel(const float* __restrict__ x)
{
    extern __shared__ char sm[];
    const u32 sb = s2u(sm);
    const int tid = threadIdx.x, lane = tid & 31, wid = tid >> 5;
    const int g = lane >> 2, t = lane & 3;
    const int l7 = lane & 7, b3 = (lane >> 3) & 1, h16 = lane >> 4;
    const int wm = wid & 3, wn = wid >> 2;
    const long tile = (long)blockIdx.x * 128;

    float4 ra[4];
    auto ldgA = [&](int c) {
#pragma unroll
        for (int it = 0; it < 2; it++) {
            int idx = tid + 512 * it, r = idx >> 3, gr = idx & 7;
            const float* p = x + (tile + r) * NC + c * 64 + gr * 8;
            ra[2*it]     = *(const float4*)p;
            ra[2*it + 1] = *(const float4*)(p + 4);
        }
    };
    auto stsA = [&](int buf) {
#pragma unroll
        for (int it = 0; it < 2; it++) {
            int idx = tid + 512 * it, r = idx >> 3, gr = idx & 7;
            uint4 h, l; split8(ra[2*it], ra[2*it + 1], h, l);
            u32 off = (u32)(r*128 + ((gr^(r&7))<<4));
            *(uint4*)(sm + PA(buf,0) + off) = h;
            *(uint4*)(sm + PA(buf,1) + off) = l;
        }
    };
    auto cpB = [&](int c, int buf) {
        const uint4* ws[2] = {(const uint4*)g_wh, (const uint4*)g_wl};
#pragma unroll
        for (int pl = 0; pl < 2; pl++)
#pragma unroll
            for (int it = 0; it < 3; it++) {
                int idx = tid + 512 * it, r = idx >> 3, gr = idx & 7;
                cpa(sb + PB(buf,pl) + r*128 + ((gr^(r&7))<<4),
                    ws[pl] + (long)r*128 + c*8 + gr);
            }
    };

    float acc[2][6][4];
#pragma unroll
    for (int i = 0; i < 2; i++)
#pragma unroll
        for (int j = 0; j < 6; j++)
#pragma unroll
            for (int e = 0; e < 4; e++) acc[i][j][e] = 0.f;

    ldgA(0); cpB(0, 0); CPC; stsA(0); CPW; __syncthreads();

    for (int c = 0; c < 16; c++) {
        if (c < 15) { ldgA(c + 1); cpB(c + 1, (c + 1) & 1); CPC; }
        const u32 Ah = sb + PA(c&1,0), Al = sb + PA(c&1,1);
        const u32 Bh = sb + PB(c&1,0), Bl = sb + PB(c&1,1);
#pragma unroll
        for (int ks = 0; ks < 4; ks++) {
            u32 ah[2][4], al[2][4];
#pragma unroll
            for (int i = 0; i < 2; i++) {
                u32 off = (u32)((32*wm + 16*i + b3*8 + l7)*128 + (((2*ks + h16) ^ l7) << 4));
                ldsm4(ah[i], Ah + off); ldsm4(al[i], Al + off);
            }
#pragma unroll
            for (int jp = 0; jp < 3; jp++) {
                u32 off = (u32)((48*wn + (2*jp + h16)*8 + l7)*128 + (((2*ks + b3) ^ l7) << 4));
                u32 bh[4], bl[4];
                ldsm4(bh, Bh + off); ldsm4(bl, Bl + off);
#pragma unroll
                for (int i = 0; i < 2; i++) {
                    mma4(acc[i][2*jp],   ah[i], bh);   mma4(acc[i][2*jp],   ah[i], bl);
                    mma4(acc[i][2*jp],   al[i], bh);
                    mma4(acc[i][2*jp+1], ah[i], bh+2); mma4(acc[i][2*jp+1], ah[i], bl+2);
                    mma4(acc[i][2*jp+1], al[i], bh+2);
                }
            }
        }
        if (c < 15) stsA((c + 1) & 1);
        CPW; __syncthreads();
    }

#pragma unroll
    for (int i = 0; i < 2; i++)
#pragma unroll
        for (int j = 0; j < 6; j++) {
            int colg = 48*wn + 8*j + 2*t;
            int tn = colg >> 6, col = colg & 63;
            float sc = (tn == 1) ? SCALE_Q : 1.f;
            u32* hp = (tn == 0) ? g_kh : (tn == 1) ? g_qh : g_vh;
            u32* lp = (tn == 0) ? g_kl : (tn == 1) ? g_ql : g_vl;
            long r0 = tile + 32*wm + 16*i + g;
            u32 h, l;
            split2(acc[i][j][0]*sc, acc[i][j][1]*sc, h, l);
            hp[(r0*64 + col) >> 1] = h; lp[(r0*64 + col) >> 1] = l;
            split2(acc[i][j][2]*sc, acc[i][j][3]*sc, h, l);
            hp[((r0+8)*64 + col) >> 1] = h; lp[((r0+8)*64 + col) >> 1] = l;
        }
}

// ---------------------------------------------------------------------------
// attn (split-KV): grid (16 qt, 8 b, 2 z). z=0 -> kv tiles [0..qt],
// z=1 -> [qt+1..2qt+1]. Warp owns 16 rows x 64 cols, warp-local softmax
// (log2 domain), P in regs. Partials -> global scratch; combine merges.
// ---------------------------------------------------------------------------
#define AQ(p)   ((p)*16384)
#define AK(b,p) (32768 + (b)*16384 + (p)*8192)
#define AV(b,p) (65536 + (b)*16384 + (p)*8192)
#define ASM 98304

__global__ __launch_bounds__(256) void attn_kernel()
{
    extern __shared__ char sm[];
    const u32 sb = s2u(sm);
    const int tid = threadIdx.x, lane = tid & 31, w = tid >> 5;
    const int g = lane >> 2, t = lane & 3;
    const int l7 = lane & 7, b3 = (lane >> 3) & 1, h16 = lane >> 4;
    const int qt = blockIdx.x, b = blockIdx.y, z = blockIdx.z;
    const int kt0 = z ? (qt + 1) : 0;
    const int kt1 = z ? (2*qt + 1) : qt;
    const long qrow0 = (long)b*NT + qt*128;

    auto cpkv = [&](int kt, int buf) {
        long rb = (long)b*NT + kt*64;
        const uint4* srcs[4] = {(const uint4*)g_kh, (const uint4*)g_kl,
                                (const uint4*)g_vh, (const uint4*)g_vl};
        u32 dsts[4] = {sb+AK(buf,0), sb+AK(buf,1), sb+AV(buf,0), sb+AV(buf,1)};
#pragma unroll
        for (int p = 0; p < 4; p++)
#pragma unroll
            for (int it = 0; it < 2; it++) {
                int idx = tid + 256*it, r = idx >> 3, gr = idx & 7;
                cpa(dsts[p] + r*128 + ((gr^(r&7))<<4), srcs[p] + (rb + r)*8 + gr);
            }
    };

    {   // Q planes + first K/V
        const uint4* qs[2] = {(const uint4*)g_qh, (const uint4*)g_ql};
#pragma unroll
        for (int p = 0; p < 2; p++)
#pragma unroll
            for (int it = 0; it < 4; it++) {
                int idx = tid + 256*it, r = idx >> 3, gr = idx & 7;
                cpa(sb + AQ(p) + r*128 + ((gr^(r&7))<<4), qs[p] + (qrow0 + r)*8 + gr);
            }
        cpkv(kt0, 0); CPC; CPW; __syncthreads();
    }

    u32 qh[4][4], ql[4][4];
#pragma unroll
    for (int ks = 0; ks < 4; ks++) {
        u32 off = (u32)((16*w + b3*8 + l7)*128 + (((2*ks + h16) ^ l7) << 4));
        ldsm4(qh[ks], sb + AQ(0) + off);
        ldsm4(ql[ks], sb + AQ(1) + off);
    }

    float O[8][4];
#pragma unroll
    for (int j = 0; j < 8; j++)
#pragma unroll
        for (int e = 0; e < 4; e++) O[j][e] = 0.f;
    float m0 = -1e30f, m1 = -1e30f, L0 = 0.f, L1 = 0.f;
    const int rfirst = qt*128 + 16*w;

    for (int kt = kt0; kt <= kt1; kt++) {
        int buf = (kt - kt0) & 1;
        if (kt < kt1) { cpkv(kt + 1, buf ^ 1); CPC; }

        if (kt*64 <= rfirst + 15) {
            const u32 KH = sb+AK(buf,0), KL = sb+AK(buf,1);
            const u32 VH = sb+AV(buf,0), VL = sb+AV(buf,1);
            float s[8][4];
#pragma unroll
            for (int j = 0; j < 8; j++)
#pragma unroll
                for (int e = 0; e < 4; e++) s[j][e] = 0.f;

#pragma unroll
            for (int ks = 0; ks < 4; ks++)
#pragma unroll
                for (int jp = 0; jp < 4; jp++) {
                    u32 off = (u32)(((2*jp + h16)*8 + l7)*128 + (((2*ks + b3) ^ l7) << 4));
                    u32 bh[4], bl[4];
                    ldsm4(bh, KH + off); ldsm4(bl, KL + off);
                    mma4(s[2*jp],   qh[ks], bh);   mma4(s[2*jp],   qh[ks], bl);
                    mma4(s[2*jp],   ql[ks], bh);
                    mma4(s[2*jp+1], qh[ks], bh+2); mma4(s[2*jp+1], qh[ks], bl+2);
                    mma4(s[2*jp+1], ql[ks], bh+2);
                }

            if (kt*64 + 63 > rfirst) {
                int r0g = rfirst + g, r1g = r0g + 8;
#pragma unroll
                for (int j = 0; j < 8; j++) {
                    int cg = kt*64 + j*8 + 2*t;
                    if (cg > r0g)     s[j][0] = -1e30f;
                    if (cg + 1 > r0g) s[j][1] = -1e30f;
                    if (cg > r1g)     s[j][2] = -1e30f;
                    if (cg + 1 > r1g) s[j][3] = -1e30f;
                }
            }

            float mx0 = -1e30f, mx1 = -1e30f;
#pragma unroll
            for (int j = 0; j < 8; j++) {
                mx0 = fmaxf(mx0, fmaxf(s[j][0], s[j][1]));
                mx1 = fmaxf(mx1, fmaxf(s[j][2], s[j][3]));
            }
            mx0 = fmaxf(mx0, __shfl_xor_sync(~0u, mx0, 1));
            mx0 = fmaxf(mx0, __shfl_xor_sync(~0u, mx0, 2));
            mx1 = fmaxf(mx1, __shfl_xor_sync(~0u, mx1, 1));
            mx1 = fmaxf(mx1, __shfl_xor_sync(~0u, mx1, 2));
            float mn0 = fmaxf(m0, mx0), mn1 = fmaxf(m1, mx1);
            float f0 = ex2f(m0 - mn0), f1 = ex2f(m1 - mn1);
            m0 = mn0; m1 = mn1;

            float s0 = 0.f, s1 = 0.f;
#pragma unroll
            for (int j = 0; j < 8; j++) {
                s[j][0] = ex2f(s[j][0] - mn0); s[j][1] = ex2f(s[j][1] - mn0);
                s[j][2] = ex2f(s[j][2] - mn1); s[j][3] = ex2f(s[j][3] - mn1);
                s0 += s[j][0] + s[j][1];
                s1 += s[j][2] + s[j][3];
            }
            s0 += __shfl_xor_sync(~0u, s0, 1); s0 += __shfl_xor_sync(~0u, s0, 2);
            s1 += __shfl_xor_sync(~0u, s1, 1); s1 += __shfl_xor_sync(~0u, s1, 2);
            L0 = L0 * f0 + s0; L1 = L1 * f1 + s1;

            u32 ph[4][4], pl2[4][4];
#pragma unroll
            for (int ks = 0; ks < 4; ks++) {
                split2(s[2*ks][0],   s[2*ks][1],   ph[ks][0], pl2[ks][0]);
                split2(s[2*ks][2],   s[2*ks][3],   ph[ks][1], pl2[ks][1]);
                split2(s[2*ks+1][0], s[2*ks+1][1], ph[ks][2], pl2[ks][2]);
                split2(s[2*ks+1][2], s[2*ks+1][3], ph[ks][3], pl2[ks][3]);
            }
#pragma unroll
            for (int j = 0; j < 8; j++) {
                O[j][0] *= f0; O[j][1] *= f0; O[j][2] *= f1; O[j][3] *= f1;
            }

#pragma unroll
            for (int ks = 0; ks < 4; ks++)
#pragma unroll
                for (int jp = 0; jp < 4; jp++) {
                    u32 off = (u32)((16*ks + b3*8 + l7)*128 + (((2*jp + h16) ^ l7) << 4));
                    u32 vh[4], vl[4];
                    ldsm4t(vh, VH + off); ldsm4t(vl, VL + off);
                    mma4(O[2*jp],   ph[ks],  vh);   mma4(O[2*jp],   ph[ks],  vl);
                    mma4(O[2*jp],   pl2[ks], vh);
                    mma4(O[2*jp+1], ph[ks],  vh+2); mma4(O[2*jp+1], ph[ks],  vl+2);
                    mma4(O[2*jp+1], pl2[ks], vh+2);
                }
        }
        CPW; __syncthreads();
    }

    // write partials (unnormalized O + m, l)
    float* Od = z ? g_O1 : g_O0;
#pragma unroll
    for (int j = 0; j < 8; j++) {
        int col = j*8 + 2*t;
        *(float2*)(Od + (qrow0 + 16*w + g)*64 + col)     = make_float2(O[j][0], O[j][1]);
        *(float2*)(Od + (qrow0 + 16*w + g + 8)*64 + col) = make_float2(O[j][2], O[j][3]);
    }
    if (t == 0) {
        float* mp = z ? g_m1 : g_m0;
        float* lp = z ? g_l1 : g_l0;
        mp[qrow0 + 16*w + g]     = m0;  lp[qrow0 + 16*w + g]     = L0;
        mp[qrow0 + 16*w + g + 8] = m1;  lp[qrow0 + 16*w + g + 8] = L1;
    }
}

// ---------------------------------------------------------------------------
// combine: out = (O0*2^(m0-M) + O1*2^(m1-M)) / (l0*2^(m0-M) + l1*2^(m1-M))
// ---------------------------------------------------------------------------
__global__ __launch_bounds__(256) void combine_kernel(float* __restrict__ out)
{
    long i = (long)blockIdx.x * 256 + threadIdx.x;   // over NR*16 float4 groups
    long row = i >> 4;
    float mA = g_m0[row], mB = g_m1[row];
    float M = fmaxf(mA, mB);
    float wA = ex2f(mA - M), wB = ex2f(mB - M);
    float inv = 1.f / (g_l0[row] * wA + g_l1[row] * wB);
    float4 a = ((const float4*)g_O0)[i];
    float4 c = ((const float4*)g_O1)[i];
    float4 o;
    o.x = (a.x * wA + c.x * wB) * inv;
    o.y = (a.y * wA + c.y * wB) * inv;
    o.z = (a.z * wA + c.z * wB) * inv;
    o.w = (a.w * wA + c.w * wB) * inv;
    ((float4*)out)[i] = o;
}

extern "C" void kernel_launch(void* const* d_in, const int* in_sizes, int n_in,
                              void* d_out, int out_size)
{
    const float* x  = (const float*)d_in[0];
    const float* Wk = (const float*)d_in[1];
    const float* Wq = (const float*)d_in[2];
    const float* Wv = (const float*)d_in[3];
    float* out = (float*)d_out;

    prepw_kernel<<<96, 256>>>(Wk, Wq, Wv);

    cudaFuncSetAttribute(proj_kernel,
                         cudaFuncAttributeMaxDynamicSharedMemorySize, PSM);
    proj_kernel<<<128, 512, PSM>>>(x);

    cudaFuncSetAttribute(attn_kernel,
                         cudaFuncAttributeMaxDynamicSharedMemorySize, ASM);
    attn_kernel<<<dim3(16, 8, 2), 256, ASM>>>();

    combine_kernel<<<NR * 16 / 256, 256>>>(out);
}